// round 13
// baseline (speedup 1.0000x reference)
#include <cuda_runtime.h>
#include <cuda_fp16.h>
#include <cstdint>

// ============================================================================
// Problem constants
// ============================================================================
#define NTOK 1024
#define HDIM 2048
#define NEXP 8
#define IEXP 1408
#define ISHA 5632

// ============================================================================
// Scratch (allocation-free rule: __device__ globals)
// ============================================================================
__device__ __half g_wgu_h[(size_t)NEXP * HDIM * 2 * IEXP];   // 92MB
__device__ __half g_swgu_h[(size_t)HDIM * 2 * ISHA];         // 46MB
__device__ __half g_wdn_h[(size_t)NEXP * IEXP * HDIM];       // 46MB
__device__ __half g_swdn_h[(size_t)ISHA * HDIM];             // 23MB
__device__ __half g_xh[(size_t)NTOK * HDIM];                 // 4MB
__device__ __half g_acts_h[(size_t)NTOK * ISHA];             // 11.5MB
__device__ __half g_actr_h[(size_t)NEXP * NTOK * IEXP];      // 23MB
__device__ float  g_eo[(size_t)NEXP * NTOK * HDIM];          // 67MB
__device__ float  g_sg[NTOK];
__device__ int    g_cnt[NEXP];
__device__ int    g_tok[NEXP * NTOK];
__device__ float  g_wt[NEXP * NTOK];
__device__ int    g_slot[NTOK * 2];

// ============================================================================
// Helpers
// ============================================================================
__device__ __forceinline__ uint32_t smem_u32(const void* p) {
    uint32_t a;
    asm("{ .reg .u64 t; cvta.to.shared.u64 t, %1; cvt.u32.u64 %0, t; }" : "=r"(a) : "l"(p));
    return a;
}

__device__ __forceinline__ void cp16(uint32_t dst, const void* src) {
    asm volatile("cp.async.cg.shared.global [%0], [%1], 16;" :: "r"(dst), "l"(src));
}
#define CP_COMMIT() asm volatile("cp.async.commit_group;" ::: "memory")
#define CP_WAIT(n)  asm volatile("cp.async.wait_group %0;" :: "n"(n) : "memory")

// m16n8k16 fp16 mma, fp32 accumulate
__device__ __forceinline__ void mma16(float* d, const uint32_t* a, const uint32_t* b) {
    asm volatile(
        "mma.sync.aligned.m16n8k16.row.col.f32.f16.f16.f32 "
        "{%0,%1,%2,%3}, {%4,%5,%6,%7}, {%8,%9}, {%0,%1,%2,%3};"
        : "+f"(d[0]), "+f"(d[1]), "+f"(d[2]), "+f"(d[3])
        : "r"(a[0]), "r"(a[1]), "r"(a[2]), "r"(a[3]), "r"(b[0]), "r"(b[1]));
}

__device__ __forceinline__ void ldsm4(uint32_t* r, uint32_t addr) {
    asm volatile("ldmatrix.sync.aligned.m8n8.x4.shared.b16 {%0,%1,%2,%3}, [%4];"
        : "=r"(r[0]), "=r"(r[1]), "=r"(r[2]), "=r"(r[3]) : "r"(addr));
}
__device__ __forceinline__ void ldsm4t(uint32_t* r, uint32_t addr) {
    asm volatile("ldmatrix.sync.aligned.m8n8.x4.trans.shared.b16 {%0,%1,%2,%3}, [%4];"
        : "=r"(r[0]), "=r"(r[1]), "=r"(r[2]), "=r"(r[3]) : "r"(addr));
}

// ============================================================================
// Small kernels
// ============================================================================
__global__ void zero_kernel() {
    if (threadIdx.x < NEXP) g_cnt[threadIdx.x] = 0;
}

// fp32 -> fp16 (rne), 8 elems per thread
__global__ void cvt_kernel(const float* __restrict__ src, __half* __restrict__ dst, int n8) {
    int idx = blockIdx.x * 256 + threadIdx.x;
    if (idx >= n8) return;
    const float4* s = reinterpret_cast<const float4*>(src) + (size_t)idx * 2;
    float4 v0 = s[0], v1 = s[1];
    __half2 h0 = __floats2half2_rn(v0.x, v0.y);
    __half2 h1 = __floats2half2_rn(v0.z, v0.w);
    __half2 h2 = __floats2half2_rn(v1.x, v1.y);
    __half2 h3 = __floats2half2_rn(v1.z, v1.w);
    uint4 o;
    o.x = *reinterpret_cast<uint32_t*>(&h0);
    o.y = *reinterpret_cast<uint32_t*>(&h1);
    o.z = *reinterpret_cast<uint32_t*>(&h2);
    o.w = *reinterpret_cast<uint32_t*>(&h3);
    reinterpret_cast<uint4*>(dst)[idx] = o;
}

// ============================================================================
// Router: softmax + top-2 -> per-expert token lists + token->slot map
// ============================================================================
__global__ void router_kernel(const float* __restrict__ x,
                              const float* __restrict__ gw,
                              const float* __restrict__ sgw) {
    const int n = blockIdx.x;
    const int tid = threadIdx.x;  // 128
    const float* xr = x + (size_t)n * HDIM;
    float acc[9];
#pragma unroll
    for (int j = 0; j < 9; j++) acc[j] = 0.f;
    for (int k = tid; k < HDIM; k += 128) {
        float xv = xr[k];
#pragma unroll
        for (int e = 0; e < NEXP; e++) acc[e] += xv * gw[k * NEXP + e];
        acc[8] += xv * sgw[k];
    }
    __shared__ float red[9][4];
#pragma unroll
    for (int j = 0; j < 9; j++) {
        float v = acc[j];
#pragma unroll
        for (int o = 16; o > 0; o >>= 1) v += __shfl_xor_sync(0xffffffffu, v, o);
        if ((tid & 31) == 0) red[j][tid >> 5] = v;
    }
    __syncthreads();
    if (tid == 0) {
        float lg[9];
#pragma unroll
        for (int j = 0; j < 9; j++) lg[j] = red[j][0] + red[j][1] + red[j][2] + red[j][3];
        float m = lg[0];
        for (int e = 1; e < NEXP; e++) m = fmaxf(m, lg[e]);
        float p[NEXP], s = 0.f;
        for (int e = 0; e < NEXP; e++) { p[e] = expf(lg[e] - m); s += p[e]; }
        for (int e = 0; e < NEXP; e++) p[e] /= s;
        int i1 = 0;
        for (int e = 1; e < NEXP; e++) if (p[e] > p[i1]) i1 = e;
        int i2 = (i1 == 0) ? 1 : 0;
        for (int e = 0; e < NEXP; e++) if (e != i1 && p[e] > p[i2]) i2 = e;
        int s1 = atomicAdd(&g_cnt[i1], 1);
        g_tok[i1 * NTOK + s1] = n;  g_wt[i1 * NTOK + s1] = p[i1];
        g_slot[n * 2] = i1 * NTOK + s1;
        int s2 = atomicAdd(&g_cnt[i2], 1);
        g_tok[i2 * NTOK + s2] = n;  g_wt[i2 * NTOK + s2] = p[i2];
        g_slot[n * 2 + 1] = i2 * NTOK + s2;
        g_sg[n] = 1.f / (1.f + expf(-lg[8]));
    }
}

// ============================================================================
// Merged gate_up GEMM + SiLU*mul, all-fp16 smem + ldmatrix
//   CTA 128m x 64f, 128 threads, 4 warps each 64m x 64n (m-half x gate/up).
//   SMEM stage (bytes): As[128][40]h =10240, Bg[32][72]h =4608, Bu same.
// ============================================================================
#define GU_AS_B 10240
#define GU_BS_B 4608
#define GU_STAGE (GU_AS_B + 2 * GU_BS_B)        // 19456 B
#define GU_SMEM (2 * GU_STAGE)                  // 38912 B

__global__ __launch_bounds__(128, 3) void gateup_all() {
    const int z = blockIdx.z;
    const int m0 = blockIdx.y * 128;
    int F, cnt, ebase = 0;
    const __half* W;
    __half* actOut;
    if (z == 0) {
        F = ISHA; cnt = NTOK; W = g_swgu_h; actOut = g_acts_h;
    } else {
        F = IEXP;
        if (blockIdx.x >= IEXP / 64) return;
        const int e = z - 1;
        cnt = g_cnt[e];
        if (m0 >= cnt) return;
        ebase = e * NTOK;
        W = g_wgu_h + (size_t)e * HDIM * 2 * IEXP;
        actOut = g_actr_h + (size_t)e * NTOK * IEXP;
    }
    const int f0 = blockIdx.x * 64;
    const int ldw = 2 * F;
    extern __shared__ char smem[];
    const int tid = threadIdx.x;
    const int wid = tid >> 5, lane = tid & 31;
    const int gid = lane >> 2, tg = lane & 3;
    const int wm = (wid & 1) * 64;
    const int uphalf = wid >> 1;
    const int grp = lane >> 3, li = lane & 7;
    const uint32_t sb = smem_u32(smem);

    // ldmatrix per-lane byte offsets
    const uint32_t laneA = (uint32_t)(((grp & 1) * 8 + li) * 80 + (grp >> 1) * 16);
    const uint32_t laneB = (uint32_t)(((grp & 1) * 8 + li) * 144 + (grp >> 1) * 16);

    // ---- staging addressing ----
    // A: 4 chunks/thread: row = (tid>>2) + i*32, q = tid&3
    const int aRow0 = tid >> 2, aQ = tid & 3;
    const __half* aSrc[4];
#pragma unroll
    for (int i = 0; i < 4; i++) {
        int row = aRow0 + i * 32;
        int t;
        if (z > 0)
            t = g_tok[ebase + ((m0 + row < cnt) ? (m0 + row) : 0)];
        else
            t = m0 + row;
        aSrc[i] = g_xh + (size_t)t * HDIM + aQ * 8;
    }
    const uint32_t aDst0 = sb + (uint32_t)(aRow0 * 80 + aQ * 16);
    // B: 4 chunks/thread: idx = tid + i*128: half = idx>>8, r = (idx>>3)&31, q = idx&7
    const __half* bSrc[4];
    uint32_t bDst[4];
#pragma unroll
    for (int i = 0; i < 4; i++) {
        int idx = tid + i * 128;
        int half = idx >> 8, r = (idx >> 3) & 31, q = idx & 7;
        bSrc[i] = W + (size_t)r * ldw + (half ? F + f0 : f0) + q * 8;
        bDst[i] = sb + (uint32_t)(GU_AS_B + half * GU_BS_B + r * 144 + q * 16);
    }

    float acc[4][8][4];
#pragma unroll
    for (int mf = 0; mf < 4; mf++)
#pragma unroll
        for (int nf = 0; nf < 8; nf++)
#pragma unroll
            for (int r = 0; r < 4; r++) acc[mf][nf][r] = 0.f;

    // ---- prologue: stage 0 ----
#pragma unroll
    for (int i = 0; i < 4; i++)
        cp16(aDst0 + (uint32_t)(i * 32 * 80), aSrc[i]);
#pragma unroll
    for (int i = 0; i < 4; i++)
        cp16(bDst[i], bSrc[i]);
    CP_COMMIT();

    int buf = 0;
    const int kIters = HDIM / 32;  // 64
    for (int kt = 0; kt < kIters; kt++) {
        if (kt + 1 < kIters) {
            const uint32_t so = (uint32_t)((buf ^ 1) * GU_STAGE);
            const int k0 = (kt + 1) * 32;
#pragma unroll
            for (int i = 0; i < 4; i++)
                cp16(aDst0 + so + (uint32_t)(i * 32 * 80), aSrc[i] + k0);
#pragma unroll
            for (int i = 0; i < 4; i++)
                cp16(bDst[i] + so, bSrc[i] + (size_t)k0 * ldw);
            CP_COMMIT();
            CP_WAIT(1);
        } else {
            CP_WAIT(0);
        }
        __syncthreads();

        const uint32_t sA = sb + (uint32_t)(buf * GU_STAGE);
        const uint32_t sB = sA + GU_AS_B + (uint32_t)(uphalf * GU_BS_B);
#pragma unroll
        for (int ks = 0; ks < 2; ks++) {
            uint32_t a[4][4];
#pragma unroll
            for (int mf = 0; mf < 4; mf++)
                ldsm4(a[mf], sA + (uint32_t)((wm + mf * 16) * 80 + ks * 32) + laneA);
#pragma unroll
            for (int p = 0; p < 4; p++) {
                uint32_t b[4];
                ldsm4t(b, sB + (uint32_t)(ks * 16 * 144 + p * 32) + laneB);
#pragma unroll
                for (int mf = 0; mf < 4; mf++) {
                    mma16(acc[mf][2 * p], a[mf], b);
                    mma16(acc[mf][2 * p + 1], a[mf], b + 2);
                }
            }
        }
        __syncthreads();
        buf ^= 1;
    }

    // ---- epilogue: up warps stash via smem (fp32), gate warps combine ----
    float* ex = reinterpret_cast<float*>(smem);
    if (uphalf) {
#pragma unroll
        for (int mf = 0; mf < 4; mf++)
#pragma unroll
            for (int h = 0; h < 2; h++) {
                int row = wm + mf * 16 + gid + h * 8;
#pragma unroll
                for (int nf = 0; nf < 8; nf++) {
                    int col = nf * 8 + 2 * tg;
                    ex[row * 72 + col]     = acc[mf][nf][2 * h];
                    ex[row * 72 + col + 1] = acc[mf][nf][2 * h + 1];
                }
            }
    }
    __syncthreads();
    if (!uphalf) {
#pragma unroll
        for (int mf = 0; mf < 4; mf++)
#pragma unroll
            for (int h = 0; h < 2; h++) {
                int row = wm + mf * 16 + gid + h * 8;
                __half* orow = actOut + (size_t)(m0 + row) * F + f0;
#pragma unroll
                for (int nf = 0; nf < 8; nf++) {
                    int col = nf * 8 + 2 * tg;
                    float g0 = acc[mf][nf][2 * h];
                    float g1 = acc[mf][nf][2 * h + 1];
                    float u0 = ex[row * 72 + col];
                    float u1 = ex[row * 72 + col + 1];
                    float s0 = g0 / (1.0f + __expf(-g0));
                    float s1 = g1 / (1.0f + __expf(-g1));
                    orow[col]     = __float2half_rn(s0 * u0);
                    orow[col + 1] = __float2half_rn(s1 * u1);
                }
            }
    }
}

// ============================================================================
// Merged down GEMM, all-fp16 smem + ldmatrix
//   CTA 128m x 128n, 128 threads, 4 warps each 64m x 64n.
//   SMEM stage: As[128][40]h =10240, Bs[32][136]h =8704.
// ============================================================================
#define DN_AS_B 10240
#define DN_BS_B 8704
#define DN_STAGE (DN_AS_B + DN_BS_B)            // 18944 B
#define DN_SMEM (2 * DN_STAGE)                  // 37888 B

__global__ __launch_bounds__(128, 3) void down_all(float* __restrict__ out) {
    const int z = blockIdx.z;
    const int m0 = blockIdx.y * 128;
    int Fk, cnt, ebase = 0;
    const __half* Wd;
    const __half* A;
    if (z == 0) {
        Fk = ISHA; cnt = NTOK; Wd = g_swdn_h; A = g_acts_h;
    } else {
        Fk = IEXP;
        const int e = z - 1;
        cnt = g_cnt[e];
        if (m0 >= cnt) return;
        ebase = e * NTOK;
        Wd = g_wdn_h + (size_t)e * IEXP * HDIM;
        A = g_actr_h + (size_t)e * NTOK * IEXP;
    }
    const int n0 = blockIdx.x * 128;
    extern __shared__ char smem[];
    const int tid = threadIdx.x;
    const int wid = tid >> 5, lane = tid & 31;
    const int gid = lane >> 2, tg = lane & 3;
    const int wm = (wid & 1) * 64;
    const int wn = (wid >> 1) * 64;
    const int grp = lane >> 3, li = lane & 7;
    const int kIters = Fk / 32;
    const uint32_t sb = smem_u32(smem);

    const uint32_t laneA = (uint32_t)(((grp & 1) * 8 + li) * 80 + (grp >> 1) * 16);
    const uint32_t laneB = (uint32_t)(((grp & 1) * 8 + li) * 272 + (grp >> 1) * 16);

    // A: 4 chunks/thread
    const int aRow0 = tid >> 2, aQ = tid & 3;
    const __half* aBase = A + (size_t)(m0 + aRow0) * Fk + aQ * 8;
    const size_t aStride = (size_t)32 * Fk;
    const uint32_t aDst0 = sb + (uint32_t)(aRow0 * 80 + aQ * 16);
    // B: 4 chunks/thread: idx: r = idx>>4 (0..31), q = idx&15
    const int bR0 = tid >> 4, bQ = tid & 15;
    const __half* bBase = Wd + (size_t)bR0 * HDIM + n0 + bQ * 8;
    const uint32_t bDst0 = sb + (uint32_t)(DN_AS_B + bR0 * 272 + bQ * 16);

    float acc[4][8][4];
#pragma unroll
    for (int mf = 0; mf < 4; mf++)
#pragma unroll
        for (int nf = 0; nf < 8; nf++)
#pragma unroll
            for (int r = 0; r < 4; r++) acc[mf][nf][r] = 0.f;

#pragma unroll
    for (int i = 0; i < 4; i++)
        cp16(aDst0 + (uint32_t)(i * 32 * 80), aBase + (size_t)i * aStride);
#pragma unroll
    for (int i = 0; i < 4; i++)
        cp16(bDst0 + (uint32_t)(i * 8 * 272), bBase + (size_t)(i * 8) * HDIM);
    CP_COMMIT();

    int buf = 0;
    for (int kt = 0; kt < kIters; kt++) {
        if (kt + 1 < kIters) {
            const uint32_t so = (uint32_t)((buf ^ 1) * DN_STAGE);
            const int k0 = (kt + 1) * 32;
#pragma unroll
            for (int i = 0; i < 4; i++)
                cp16(aDst0 + so + (uint32_t)(i * 32 * 80),
                     aBase + (size_t)i * aStride + k0);
#pragma unroll
            for (int i = 0; i < 4; i++)
                cp16(bDst0 + so + (uint32_t)(i * 8 * 272),
                     bBase + (size_t)(k0 + i * 8) * HDIM);
            CP_COMMIT();
            CP_WAIT(1);
        } else {
            CP_WAIT(0);
        }
        __syncthreads();

        const uint32_t sA = sb + (uint32_t)(buf * DN_STAGE);
        const uint32_t sB = sA + DN_AS_B;
#pragma unroll
        for (int ks = 0; ks < 2; ks++) {
            uint32_t a[4][4];
#pragma unroll
            for (int mf = 0; mf < 4; mf++)
                ldsm4(a[mf], sA + (uint32_t)((wm + mf * 16) * 80 + ks * 32) + laneA);
#pragma unroll
            for (int p = 0; p < 4; p++) {
                uint32_t b[4];
                ldsm4t(b, sB + (uint32_t)(ks * 16 * 272 + (wn + p * 16) * 2) + laneB);
#pragma unroll
                for (int mf = 0; mf < 4; mf++) {
                    mma16(acc[mf][2 * p], a[mf], b);
                    mma16(acc[mf][2 * p + 1], a[mf], b + 2);
                }
            }
        }
        __syncthreads();
        buf ^= 1;
    }

    // Epilogue
#pragma unroll
    for (int mf = 0; mf < 4; mf++) {
#pragma unroll
        for (int h = 0; h < 2; h++) {
            int slot = m0 + wm + mf * 16 + gid + h * 8;
            float wv;
            float* orow;
            if (z == 0) {
                wv = g_sg[slot];
                orow = out + (size_t)slot * HDIM;
            } else {
                if (slot >= cnt) continue;
                wv = g_wt[ebase + slot];
                orow = g_eo + (size_t)(ebase + slot) * HDIM;
            }
#pragma unroll
            for (int nf = 0; nf < 8; nf++) {
                int col = n0 + wn + nf * 8 + 2 * tg;
                orow[col]     = wv * acc[mf][nf][2 * h];
                orow[col + 1] = wv * acc[mf][nf][2 * h + 1];
            }
        }
    }
}

// ============================================================================
// Combine: out[token] += g_eo[slotA] + g_eo[slotB]   (weights pre-applied)
// ============================================================================
__global__ void combine_kernel(float* __restrict__ out) {
    const int n = blockIdx.x;
    const int tid = threadIdx.x;  // 256
    const size_t r0 = (size_t)g_slot[n * 2] * HDIM;
    const size_t r1 = (size_t)g_slot[n * 2 + 1] * HDIM;
    float4* o = reinterpret_cast<float4*>(out + (size_t)n * HDIM);
    const float4* e0 = reinterpret_cast<const float4*>(g_eo + r0);
    const float4* e1 = reinterpret_cast<const float4*>(g_eo + r1);
#pragma unroll
    for (int i = 0; i < 2; i++) {
        int idx = tid + i * 256;
        float4 v = o[idx], a = e0[idx], b = e1[idx];
        v.x += a.x + b.x; v.y += a.y + b.y;
        v.z += a.z + b.z; v.w += a.w + b.w;
        o[idx] = v;
    }
}

// ============================================================================
// Launch
// ============================================================================
extern "C" void kernel_launch(void* const* d_in, const int* in_sizes, int n_in,
                              void* d_out, int out_size) {
    const float* x = (const float*)d_in[0];       // [1024, 2048]
    const float* gw = (const float*)d_in[1];      // [2048, 8]
    const float* wgu = (const float*)d_in[2];     // [8, 2048, 2816]
    const float* wdn = (const float*)d_in[3];     // [8, 1408, 2048]
    const float* swgu = (const float*)d_in[4];    // [2048, 11264]
    const float* swdn = (const float*)d_in[5];    // [5632, 2048]
    const float* sgw = (const float*)d_in[6];     // [2048, 1]
    float* out = (float*)d_out;                   // [1024, 2048]

    static __half* wgu_h = nullptr;  // resolved device-symbol addresses
    __half *p_wgu, *p_swgu, *p_wdn, *p_swdn, *p_xh;
    cudaGetSymbolAddress((void**)&p_wgu, g_wgu_h);
    cudaGetSymbolAddress((void**)&p_swgu, g_swgu_h);
    cudaGetSymbolAddress((void**)&p_wdn, g_wdn_h);
    cudaGetSymbolAddress((void**)&p_swdn, g_swdn_h);
    cudaGetSymbolAddress((void**)&p_xh, g_xh);
    (void)wgu_h;

    cudaFuncSetAttribute(gateup_all, cudaFuncAttributeMaxDynamicSharedMemorySize, GU_SMEM);
    cudaFuncSetAttribute(down_all, cudaFuncAttributeMaxDynamicSharedMemorySize, DN_SMEM);

    zero_kernel<<<1, 32>>>();
    router_kernel<<<NTOK, 128>>>(x, gw, sgw);

    // fp32 -> fp16 conversions (weights + x)
    {
        int n8;
        n8 = NEXP * HDIM * 2 * IEXP / 8;
        cvt_kernel<<<(n8 + 255) / 256, 256>>>(wgu, p_wgu, n8);
        n8 = HDIM * 2 * ISHA / 8;
        cvt_kernel<<<(n8 + 255) / 256, 256>>>(swgu, p_swgu, n8);
        n8 = NEXP * IEXP * HDIM / 8;
        cvt_kernel<<<(n8 + 255) / 256, 256>>>(wdn, p_wdn, n8);
        n8 = ISHA * HDIM / 8;
        cvt_kernel<<<(n8 + 255) / 256, 256>>>(swdn, p_swdn, n8);
        n8 = NTOK * HDIM / 8;
        cvt_kernel<<<(n8 + 255) / 256, 256>>>(x, p_xh, n8);
    }

    // All gate_up GEMMs (shared z=0 + experts z=1..8) in one launch.
    gateup_all<<<dim3(ISHA / 64, NTOK / 128, 1 + NEXP), 128, GU_SMEM>>>();

    // All down GEMMs in one launch: z=0 writes out, z>=1 writes g_eo (disjoint).
    down_all<<<dim3(HDIM / 128, NTOK / 128, 1 + NEXP), 128, DN_SMEM>>>(out);

    // Gather the two expert rows per token into out.
    combine_kernel<<<NTOK, 256>>>(out);
}

// round 14
// speedup vs baseline: 1.4371x; 1.4371x over previous
#include <cuda_runtime.h>
#include <cstdint>

// ============================================================================
// Problem constants
// ============================================================================
#define NTOK 1024
#define HDIM 2048
#define NEXP 8
#define IEXP 1408
#define ISHA 5632
#define DN_KCH 1408          // uniform down-GEMM K chunk (= IEXP, = ISHA/4)

// ============================================================================
// Scratch (allocation-free rule: __device__ globals)
// ============================================================================
__device__ float g_acts[(size_t)NTOK * ISHA];          // shared act (23MB)
__device__ float g_actr[(size_t)NEXP * NTOK * IEXP];   // routed act (46MB)
__device__ float g_eo[(size_t)NEXP * NTOK * HDIM];     // routed expert out (67MB)
__device__ float g_sp[(size_t)4 * NTOK * HDIM];        // shared down partials (32MB)
__device__ float g_sg[NTOK];
__device__ int   g_cnt[NEXP];
__device__ int   g_tok[NEXP * NTOK];                   // expert -> token list
__device__ float g_wt[NEXP * NTOK];                    // expert -> routing weight / slot
__device__ int   g_slot[NTOK * 2];                     // token -> 2 global slots

// ============================================================================
// Helpers
// ============================================================================
__device__ __forceinline__ uint32_t smem_u32(const void* p) {
    uint32_t a;
    asm("{ .reg .u64 t; cvta.to.shared.u64 t, %1; cvt.u32.u64 %0, t; }" : "=r"(a) : "l"(p));
    return a;
}

// Pack two fp32 -> f16x2 (rne). Order consistent between A and B, so any
// lo/hi convention cancels in the MMA dot product.
__device__ __forceinline__ uint32_t pack_h2(float a, float b) {
    uint32_t r;
    asm("cvt.rn.f16x2.f32 %0, %1, %2;" : "=r"(r) : "f"(b), "f"(a));
    return r;
}

__device__ __forceinline__ void cp16(uint32_t dst, const float* src) {
    asm volatile("cp.async.cg.shared.global [%0], [%1], 16;" :: "r"(dst), "l"(src));
}
#define CP_COMMIT() asm volatile("cp.async.commit_group;" ::: "memory")
#define CP_WAIT(n)  asm volatile("cp.async.wait_group %0;" :: "n"(n) : "memory")

// m16n8k16 fp16 mma, fp32 accumulate
__device__ __forceinline__ void mma16(float* d, const uint32_t* a, const uint32_t* b) {
    asm volatile(
        "mma.sync.aligned.m16n8k16.row.col.f32.f16.f16.f32 "
        "{%0,%1,%2,%3}, {%4,%5,%6,%7}, {%8,%9}, {%0,%1,%2,%3};"
        : "+f"(d[0]), "+f"(d[1]), "+f"(d[2]), "+f"(d[3])
        : "r"(a[0]), "r"(a[1]), "r"(a[2]), "r"(a[3]), "r"(b[0]), "r"(b[1]));
}

// ============================================================================
// Small kernels
// ============================================================================
__global__ void zero_kernel() {
    if (threadIdx.x < NEXP) g_cnt[threadIdx.x] = 0;
}

// ============================================================================
// Router: softmax + top-2 -> per-expert token lists + token->slot map
// ============================================================================
__global__ void router_kernel(const float* __restrict__ x,
                              const float* __restrict__ gw,
                              const float* __restrict__ sgw) {
    const int n = blockIdx.x;
    const int tid = threadIdx.x;  // 128
    const float* xr = x + (size_t)n * HDIM;
    float acc[9];
#pragma unroll
    for (int j = 0; j < 9; j++) acc[j] = 0.f;
    for (int k = tid; k < HDIM; k += 128) {
        float xv = xr[k];
#pragma unroll
        for (int e = 0; e < NEXP; e++) acc[e] += xv * gw[k * NEXP + e];
        acc[8] += xv * sgw[k];
    }
    __shared__ float red[9][4];
#pragma unroll
    for (int j = 0; j < 9; j++) {
        float v = acc[j];
#pragma unroll
        for (int o = 16; o > 0; o >>= 1) v += __shfl_xor_sync(0xffffffffu, v, o);
        if ((tid & 31) == 0) red[j][tid >> 5] = v;
    }
    __syncthreads();
    if (tid == 0) {
        float lg[9];
#pragma unroll
        for (int j = 0; j < 9; j++) lg[j] = red[j][0] + red[j][1] + red[j][2] + red[j][3];
        float m = lg[0];
        for (int e = 1; e < NEXP; e++) m = fmaxf(m, lg[e]);
        float p[NEXP], s = 0.f;
        for (int e = 0; e < NEXP; e++) { p[e] = expf(lg[e] - m); s += p[e]; }
        for (int e = 0; e < NEXP; e++) p[e] /= s;
        int i1 = 0;
        for (int e = 1; e < NEXP; e++) if (p[e] > p[i1]) i1 = e;
        int i2 = (i1 == 0) ? 1 : 0;
        for (int e = 0; e < NEXP; e++) if (e != i1 && p[e] > p[i2]) i2 = e;
        int s1 = atomicAdd(&g_cnt[i1], 1);
        g_tok[i1 * NTOK + s1] = n;  g_wt[i1 * NTOK + s1] = p[i1];
        g_slot[n * 2] = i1 * NTOK + s1;
        int s2 = atomicAdd(&g_cnt[i2], 1);
        g_tok[i2 * NTOK + s2] = n;  g_wt[i2 * NTOK + s2] = p[i2];
        g_slot[n * 2 + 1] = i2 * NTOK + s2;
        g_sg[n] = 1.f / (1.f + expf(-lg[8]));
    }
}

// ============================================================================
// Merged gate_up GEMM + SiLU*mul  (z=0: shared, z=1..8: expert z-1)
//   fp16 m16n8k16 MMA, fp32 smem staging, cvt at fragment load.
//   CTA 128m x 64f, 128 threads, 4 warps each 64m x 64n (m-half x gate/up).
//   SMEM stage: As[128][40], B 2 x [32][68]. 2-stage cp.async.
// ============================================================================
#define GU_APAD 40
#define GU_BPAD 68
#define GU_ASZ (128 * GU_APAD)                  // 5120 floats
#define GU_BSZ (32 * GU_BPAD)                   // 2176 floats
#define GU_BUF (GU_ASZ + 2 * GU_BSZ)            // 9472 floats / stage
#define GU_SMEM (2 * GU_BUF * 4)                // 75776 bytes

__global__ __launch_bounds__(128, 3) void gateup_all(const float* __restrict__ X,
                                                     const float* __restrict__ Wsh,
                                                     const float* __restrict__ Wex) {
    const int z = blockIdx.z;
    const int m0 = blockIdx.y * 128;
    int F, cnt, ebase = 0;
    const float* W;
    float* actOut;
    if (z == 0) {
        F = ISHA; cnt = NTOK; W = Wsh; actOut = g_acts;
    } else {
        F = IEXP;
        if (blockIdx.x >= IEXP / 64) return;
        const int e = z - 1;
        cnt = g_cnt[e];
        if (m0 >= cnt) return;
        ebase = e * NTOK;
        W = Wex + (size_t)e * HDIM * 2 * IEXP;
        actOut = g_actr + (size_t)e * NTOK * IEXP;
    }
    const int f0 = blockIdx.x * 64;
    const int ldw = 2 * F;
    extern __shared__ float smem[];
    const int tid = threadIdx.x;
    const int wid = tid >> 5, lane = tid & 31;
    const int gid = lane >> 2, tg = lane & 3;
    const int wm = (wid & 1) * 64;       // m-half
    const int uphalf = wid >> 1;         // 0 = gate, 1 = up
    const uint32_t sb = smem_u32(smem);

    // ---- staging addressing ----
    const int aRow0 = tid >> 3, aQ = tid & 7;
    uint32_t aByte[8];                    // token row byte offsets into X
#pragma unroll
    for (int i = 0; i < 8; i++) {
        int row = aRow0 + 16 * i;
        int t;
        if (z > 0)
            t = g_tok[ebase + ((m0 + row < cnt) ? (m0 + row) : 0)];
        else
            t = m0 + row;
        aByte[i] = (uint32_t)t * (HDIM * 4);
    }
    const char* xbase = (const char*)X + aQ * 16;
    const uint32_t aDst0 = sb + (uint32_t)(aRow0 * GU_APAD + aQ * 4) * 4;
    const int bR0 = tid >> 4, bQ = tid & 15;
    const float* bBase = W + (size_t)bR0 * ldw + f0 + bQ * 4;
    const uint32_t bDst0 = sb + (uint32_t)(GU_ASZ + bR0 * GU_BPAD + bQ * 4) * 4;

    float acc[4][8][4];
#pragma unroll
    for (int mf = 0; mf < 4; mf++)
#pragma unroll
        for (int nf = 0; nf < 8; nf++)
#pragma unroll
            for (int r = 0; r < 4; r++) acc[mf][nf][r] = 0.f;

    // ---- prologue: stage 0 ----
#pragma unroll
    for (int i = 0; i < 8; i++)
        cp16(aDst0 + (uint32_t)(i * 16 * GU_APAD * 4),
             (const float*)(xbase + aByte[i]));
#pragma unroll
    for (int i = 0; i < 8; i++) {
        int half = i >> 2, rr = i & 3;
        cp16(bDst0 + (uint32_t)((half * GU_BSZ + rr * 8 * GU_BPAD) * 4),
             bBase + (size_t)(half ? F : 0) + (size_t)(rr * 8) * ldw);
    }
    CP_COMMIT();

    int buf = 0;
    const int kIters = HDIM / 32;  // 64
    for (int kt = 0; kt < kIters; kt++) {
        if (kt + 1 < kIters) {
            const uint32_t bufOff = (uint32_t)(((buf ^ 1) * GU_BUF) * 4);
            const int k0 = (kt + 1) * 32;
#pragma unroll
            for (int i = 0; i < 8; i++)
                cp16(aDst0 + bufOff + (uint32_t)(i * 16 * GU_APAD * 4),
                     (const float*)(xbase + aByte[i]) + k0);
#pragma unroll
            for (int i = 0; i < 8; i++) {
                int half = i >> 2, rr = i & 3;
                cp16(bDst0 + bufOff + (uint32_t)((half * GU_BSZ + rr * 8 * GU_BPAD) * 4),
                     bBase + (size_t)(half ? F : 0) + (size_t)(k0 + rr * 8) * ldw);
            }
            CP_COMMIT();
            CP_WAIT(1);
        } else {
            CP_WAIT(0);
        }
        __syncthreads();

        const float* As = smem + buf * GU_BUF;
        const float* Bs = As + GU_ASZ + uphalf * GU_BSZ;
        // 2 x k16 steps per 32-wide k-tile
#pragma unroll
        for (int ks = 0; ks < 2; ks++) {
            const int k0 = ks * 16;
            uint32_t a[4][4];
#pragma unroll
            for (int mf = 0; mf < 4; mf++) {
                int r = wm + mf * 16 + gid;
                float2 p0 = *(const float2*)(As + r * GU_APAD + k0 + 2 * tg);
                float2 p1 = *(const float2*)(As + (r + 8) * GU_APAD + k0 + 2 * tg);
                float2 p2 = *(const float2*)(As + r * GU_APAD + k0 + 2 * tg + 8);
                float2 p3 = *(const float2*)(As + (r + 8) * GU_APAD + k0 + 2 * tg + 8);
                a[mf][0] = pack_h2(p0.x, p0.y);
                a[mf][1] = pack_h2(p1.x, p1.y);
                a[mf][2] = pack_h2(p2.x, p2.y);
                a[mf][3] = pack_h2(p3.x, p3.y);
            }
#pragma unroll
            for (int nf = 0; nf < 8; nf++) {
                int n = nf * 8 + gid;
                uint32_t b[2];
                b[0] = pack_h2(Bs[(k0 + 2 * tg) * GU_BPAD + n],
                               Bs[(k0 + 2 * tg + 1) * GU_BPAD + n]);
                b[1] = pack_h2(Bs[(k0 + 2 * tg + 8) * GU_BPAD + n],
                               Bs[(k0 + 2 * tg + 9) * GU_BPAD + n]);
#pragma unroll
                for (int mf = 0; mf < 4; mf++) mma16(acc[mf][nf], a[mf], b);
            }
        }
        __syncthreads();
        buf ^= 1;
    }

    // ---- epilogue: exchange up through smem, gate warps combine ----
    if (uphalf) {
#pragma unroll
        for (int mf = 0; mf < 4; mf++)
#pragma unroll
            for (int h = 0; h < 2; h++) {
                int row = wm + mf * 16 + gid + h * 8;
#pragma unroll
                for (int nf = 0; nf < 8; nf++) {
                    int col = nf * 8 + 2 * tg;
                    smem[row * 72 + col]     = acc[mf][nf][2 * h];
                    smem[row * 72 + col + 1] = acc[mf][nf][2 * h + 1];
                }
            }
    }
    __syncthreads();
    if (!uphalf) {
#pragma unroll
        for (int mf = 0; mf < 4; mf++)
#pragma unroll
            for (int h = 0; h < 2; h++) {
                int row = wm + mf * 16 + gid + h * 8;
                float* orow = actOut + (size_t)(m0 + row) * F + f0;
#pragma unroll
                for (int nf = 0; nf < 8; nf++) {
                    int col = nf * 8 + 2 * tg;
                    float g0 = acc[mf][nf][2 * h];
                    float g1 = acc[mf][nf][2 * h + 1];
                    float u0 = smem[row * 72 + col];
                    float u1 = smem[row * 72 + col + 1];
                    float s0 = g0 / (1.0f + __expf(-g0));
                    float s1 = g1 / (1.0f + __expf(-g1));
                    orow[col]     = s0 * u0;
                    orow[col + 1] = s1 * u1;
                }
            }
    }
}

// ============================================================================
// Merged down GEMM, uniform split-K:
//   z=0..3 : shared-expert K-chunk z (K window [z*1408, (z+1)*1408)) -> g_sp[z]
//   z=4..11: expert z-4 (K=1408)                                     -> g_eo
//   All CTAs: 44 k-iters -> no straggler tail.
//   CTA 128m x 128n, 128 threads, 4 warps each 64m x 64n.
//   SMEM stage: As[128][40], Bs[32][132]. 2-stage.
// ============================================================================
#define DN_APAD 40
#define DN_BPAD 132
#define DN_ASZ (128 * DN_APAD)                  // 5120 floats
#define DN_BSZ (32 * DN_BPAD)                   // 4224 floats
#define DN_BUF (DN_ASZ + DN_BSZ)                // 9344 floats / stage
#define DN_SMEM (2 * DN_BUF * 4)                // 74752 bytes

__global__ __launch_bounds__(128, 3) void down_all(const float* __restrict__ Wdsh,
                                                   const float* __restrict__ Wdex) {
    const int z = blockIdx.z;
    const int m0 = blockIdx.y * 128;
    int cnt, lda, ebase = 0;
    const float* Wd;
    const float* A;
    float* dstBase;
    if (z < 4) {
        cnt = NTOK;
        lda = ISHA;
        A = g_acts + (size_t)z * DN_KCH;                  // K-window offset
        Wd = Wdsh + (size_t)(z * DN_KCH) * HDIM;
        dstBase = g_sp + (size_t)z * NTOK * HDIM;
    } else {
        const int e = z - 4;
        cnt = g_cnt[e];
        if (m0 >= cnt) return;
        lda = IEXP;
        ebase = e * NTOK;
        A = g_actr + (size_t)e * NTOK * IEXP;
        Wd = Wdex + (size_t)e * IEXP * HDIM;
        dstBase = g_eo;
    }
    const int n0 = blockIdx.x * 128;
    extern __shared__ float smem[];
    const int tid = threadIdx.x;
    const int wid = tid >> 5, lane = tid & 31;
    const int gid = lane >> 2, tg = lane & 3;
    const int wm = (wid & 1) * 64;
    const int wn = (wid >> 1) * 64;
    const int kIters = DN_KCH / 32;  // 44, uniform
    const uint32_t sb = smem_u32(smem);

    const int aRow0 = tid >> 3, aQ = tid & 7;
    const float* aBase = A + (size_t)(m0 + aRow0) * lda + aQ * 4;
    const size_t aStride = (size_t)16 * lda;
    const uint32_t aDst0 = sb + (uint32_t)(aRow0 * DN_APAD + aQ * 4) * 4;
    const int bR0 = tid >> 5, bQ = tid & 31;
    const float* bBase = Wd + (size_t)bR0 * HDIM + n0 + bQ * 4;
    const uint32_t bDst0 = sb + (uint32_t)(DN_ASZ + bR0 * DN_BPAD + bQ * 4) * 4;

    float acc[4][8][4];
#pragma unroll
    for (int mf = 0; mf < 4; mf++)
#pragma unroll
        for (int nf = 0; nf < 8; nf++)
#pragma unroll
            for (int r = 0; r < 4; r++) acc[mf][nf][r] = 0.f;

#pragma unroll
    for (int i = 0; i < 8; i++)
        cp16(aDst0 + (uint32_t)(i * 16 * DN_APAD * 4), aBase + (size_t)i * aStride);
#pragma unroll
    for (int i = 0; i < 8; i++)
        cp16(bDst0 + (uint32_t)(i * 4 * DN_BPAD * 4), bBase + (size_t)(i * 4) * HDIM);
    CP_COMMIT();

    int buf = 0;
    for (int kt = 0; kt < kIters; kt++) {
        if (kt + 1 < kIters) {
            const uint32_t bufOff = (uint32_t)(((buf ^ 1) * DN_BUF) * 4);
            const int k0 = (kt + 1) * 32;
#pragma unroll
            for (int i = 0; i < 8; i++)
                cp16(aDst0 + bufOff + (uint32_t)(i * 16 * DN_APAD * 4),
                     aBase + (size_t)i * aStride + k0);
#pragma unroll
            for (int i = 0; i < 8; i++)
                cp16(bDst0 + bufOff + (uint32_t)(i * 4 * DN_BPAD * 4),
                     bBase + (size_t)(k0 + i * 4) * HDIM);
            CP_COMMIT();
            CP_WAIT(1);
        } else {
            CP_WAIT(0);
        }
        __syncthreads();

        const float* As = smem + buf * DN_BUF;
        const float* Bs = As + DN_ASZ;
#pragma unroll
        for (int ks = 0; ks < 2; ks++) {
            const int k0 = ks * 16;
            uint32_t a[4][4];
#pragma unroll
            for (int mf = 0; mf < 4; mf++) {
                int r = wm + mf * 16 + gid;
                float2 p0 = *(const float2*)(As + r * DN_APAD + k0 + 2 * tg);
                float2 p1 = *(const float2*)(As + (r + 8) * DN_APAD + k0 + 2 * tg);
                float2 p2 = *(const float2*)(As + r * DN_APAD + k0 + 2 * tg + 8);
                float2 p3 = *(const float2*)(As + (r + 8) * DN_APAD + k0 + 2 * tg + 8);
                a[mf][0] = pack_h2(p0.x, p0.y);
                a[mf][1] = pack_h2(p1.x, p1.y);
                a[mf][2] = pack_h2(p2.x, p2.y);
                a[mf][3] = pack_h2(p3.x, p3.y);
            }
#pragma unroll
            for (int nf = 0; nf < 8; nf++) {
                int n = wn + nf * 8 + gid;
                uint32_t b[2];
                b[0] = pack_h2(Bs[(k0 + 2 * tg) * DN_BPAD + n],
                               Bs[(k0 + 2 * tg + 1) * DN_BPAD + n]);
                b[1] = pack_h2(Bs[(k0 + 2 * tg + 8) * DN_BPAD + n],
                               Bs[(k0 + 2 * tg + 9) * DN_BPAD + n]);
#pragma unroll
                for (int mf = 0; mf < 4; mf++) mma16(acc[mf][nf], a[mf], b);
            }
        }
        __syncthreads();
        buf ^= 1;
    }

    // Epilogue
#pragma unroll
    for (int mf = 0; mf < 4; mf++) {
#pragma unroll
        for (int h = 0; h < 2; h++) {
            int slot = m0 + wm + mf * 16 + gid + h * 8;
            if (z < 4) {
                // shared partial: store raw accumulators (scaled in combine)
                float* orow = dstBase + (size_t)slot * HDIM;
#pragma unroll
                for (int nf = 0; nf < 8; nf++) {
                    int col = n0 + wn + nf * 8 + 2 * tg;
                    orow[col]     = acc[mf][nf][2 * h];
                    orow[col + 1] = acc[mf][nf][2 * h + 1];
                }
            } else {
                if (slot >= cnt) continue;
                float wv = g_wt[ebase + slot];
                float* orow = dstBase + (size_t)(ebase + slot) * HDIM;
#pragma unroll
                for (int nf = 0; nf < 8; nf++) {
                    int col = n0 + wn + nf * 8 + 2 * tg;
                    orow[col]     = wv * acc[mf][nf][2 * h];
                    orow[col + 1] = wv * acc[mf][nf][2 * h + 1];
                }
            }
        }
    }
}

// ============================================================================
// Combine: out[token] = sg * (sp0+sp1+sp2+sp3) + eo[slotA] + eo[slotB]
// ============================================================================
__global__ void combine_kernel(float* __restrict__ out) {
    const int n = blockIdx.x;
    const int tid = threadIdx.x;  // 256
    const float sg = g_sg[n];
    const size_t rowOff = (size_t)n * (HDIM / 4);
    const size_t r0 = (size_t)g_slot[n * 2] * (HDIM / 4);
    const size_t r1 = (size_t)g_slot[n * 2 + 1] * (HDIM / 4);
    const float4* sp = reinterpret_cast<const float4*>(g_sp);
    const float4* eo = reinterpret_cast<const float4*>(g_eo);
    float4* o = reinterpret_cast<float4*>(out) + rowOff;
    const size_t spStride = (size_t)NTOK * (HDIM / 4);
#pragma unroll
    for (int i = 0; i < 2; i++) {
        int idx = tid + i * 256;
        float4 p0 = sp[rowOff + idx];
        float4 p1 = sp[spStride + rowOff + idx];
        float4 p2 = sp[2 * spStride + rowOff + idx];
        float4 p3 = sp[3 * spStride + rowOff + idx];
        float4 a = eo[r0 + idx], b = eo[r1 + idx];
        float4 v;
        v.x = sg * (p0.x + p1.x + p2.x + p3.x) + a.x + b.x;
        v.y = sg * (p0.y + p1.y + p2.y + p3.y) + a.y + b.y;
        v.z = sg * (p0.z + p1.z + p2.z + p3.z) + a.z + b.z;
        v.w = sg * (p0.w + p1.w + p2.w + p3.w) + a.w + b.w;
        o[idx] = v;
    }
}

// ============================================================================
// Launch
// ============================================================================
extern "C" void kernel_launch(void* const* d_in, const int* in_sizes, int n_in,
                              void* d_out, int out_size) {
    const float* x = (const float*)d_in[0];       // [1024, 2048]
    const float* gw = (const float*)d_in[1];      // [2048, 8]
    const float* wgu = (const float*)d_in[2];     // [8, 2048, 2816]
    const float* wdn = (const float*)d_in[3];     // [8, 1408, 2048]
    const float* swgu = (const float*)d_in[4];    // [2048, 11264]
    const float* swdn = (const float*)d_in[5];    // [5632, 2048]
    const float* sgw = (const float*)d_in[6];     // [2048, 1]
    float* out = (float*)d_out;                   // [1024, 2048]

    cudaFuncSetAttribute(gateup_all, cudaFuncAttributeMaxDynamicSharedMemorySize, GU_SMEM);
    cudaFuncSetAttribute(down_all, cudaFuncAttributeMaxDynamicSharedMemorySize, DN_SMEM);

    zero_kernel<<<1, 32>>>();
    router_kernel<<<NTOK, 128>>>(x, gw, sgw);

    // All gate_up GEMMs (shared z=0 + experts z=1..8) in one launch.
    gateup_all<<<dim3(ISHA / 64, NTOK / 128, 1 + NEXP), 128, GU_SMEM>>>(x, swgu, wgu);

    // All down GEMMs, uniform K=1408 chunks:
    //   z=0..3 shared partials -> g_sp, z=4..11 experts -> g_eo.
    down_all<<<dim3(HDIM / 128, NTOK / 128, 4 + NEXP), 128, DN_SMEM>>>(swdn, wdn);

    // Final combine: shared partial sum * sigmoid gate + two expert rows.
    combine_kernel<<<NTOK, 256>>>(out);
}

// round 15
// speedup vs baseline: 1.5654x; 1.0893x over previous
#include <cuda_runtime.h>
#include <cuda_fp16.h>
#include <cstdint>

// ============================================================================
// Problem constants
// ============================================================================
#define NTOK 1024
#define HDIM 2048
#define NEXP 8
#define IEXP 1408
#define ISHA 5632
#define DN_KCH 1408          // uniform down-GEMM K chunk (= IEXP, = ISHA/4)

// ============================================================================
// Scratch (allocation-free rule: __device__ globals)
// ============================================================================
__device__ __half g_xh[(size_t)NTOK * HDIM];             // x in fp16 (4MB)
__device__ __half g_acts_h[(size_t)NTOK * ISHA];         // shared act fp16 (11.5MB)
__device__ __half g_actr_h[(size_t)NEXP * NTOK * IEXP];  // routed act fp16 (23MB)
__device__ float  g_eo[(size_t)NEXP * NTOK * HDIM];      // routed expert out (67MB)
__device__ float  g_sp[(size_t)4 * NTOK * HDIM];         // shared down partials (32MB)
__device__ float  g_sg[NTOK];
__device__ int    g_cnt[NEXP];
__device__ int    g_tok[NEXP * NTOK];
__device__ float  g_wt[NEXP * NTOK];
__device__ int    g_slot[NTOK * 2];

// ============================================================================
// Helpers
// ============================================================================
__device__ __forceinline__ uint32_t smem_u32(const void* p) {
    uint32_t a;
    asm("{ .reg .u64 t; cvta.to.shared.u64 t, %1; cvt.u32.u64 %0, t; }" : "=r"(a) : "l"(p));
    return a;
}

// Pack two fp32 -> f16x2 (rne), B-side fragment build.
__device__ __forceinline__ uint32_t pack_h2(float a, float b) {
    uint32_t r;
    asm("cvt.rn.f16x2.f32 %0, %1, %2;" : "=r"(r) : "f"(b), "f"(a));
    return r;
}

__device__ __forceinline__ void cp16(uint32_t dst, const void* src) {
    asm volatile("cp.async.cg.shared.global [%0], [%1], 16;" :: "r"(dst), "l"(src));
}
#define CP_COMMIT() asm volatile("cp.async.commit_group;" ::: "memory")
#define CP_WAIT(n)  asm volatile("cp.async.wait_group %0;" :: "n"(n) : "memory")

// m16n8k16 fp16 mma, fp32 accumulate
__device__ __forceinline__ void mma16(float* d, const uint32_t* a, const uint32_t* b) {
    asm volatile(
        "mma.sync.aligned.m16n8k16.row.col.f32.f16.f16.f32 "
        "{%0,%1,%2,%3}, {%4,%5,%6,%7}, {%8,%9}, {%0,%1,%2,%3};"
        : "+f"(d[0]), "+f"(d[1]), "+f"(d[2]), "+f"(d[3])
        : "r"(a[0]), "r"(a[1]), "r"(a[2]), "r"(a[3]), "r"(b[0]), "r"(b[1]));
}

// A-fragment load: m16 x k16 fp16 tile in one instruction.
// lane offset: (lane%16)*pitch + (lane/16)*16  -> frags in mma order.
__device__ __forceinline__ void ldsm4(uint32_t* r, uint32_t addr) {
    asm volatile("ldmatrix.sync.aligned.m8n8.x4.shared.b16 {%0,%1,%2,%3}, [%4];"
        : "=r"(r[0]), "=r"(r[1]), "=r"(r[2]), "=r"(r[3]) : "r"(addr));
}

// ============================================================================
// Small kernels
// ============================================================================
__global__ void zero_kernel() {
    if (threadIdx.x < NEXP) g_cnt[threadIdx.x] = 0;
}

// x fp32 -> fp16 (rne), 8 elems per thread
__global__ void cvtx_kernel(const float* __restrict__ x) {
    int idx = blockIdx.x * 256 + threadIdx.x;   // 1024 blocks
    const float4* s = reinterpret_cast<const float4*>(x) + (size_t)idx * 2;
    float4 v0 = s[0], v1 = s[1];
    uint4 o;
    o.x = pack_h2(v0.x, v0.y);
    o.y = pack_h2(v0.z, v0.w);
    o.z = pack_h2(v1.x, v1.y);
    o.w = pack_h2(v1.z, v1.w);
    reinterpret_cast<uint4*>(g_xh)[idx] = o;
}

// ============================================================================
// Router: softmax + top-2 -> per-expert token lists + token->slot map
// ============================================================================
__global__ void router_kernel(const float* __restrict__ x,
                              const float* __restrict__ gw,
                              const float* __restrict__ sgw) {
    const int n = blockIdx.x;
    const int tid = threadIdx.x;  // 128
    const float* xr = x + (size_t)n * HDIM;
    float acc[9];
#pragma unroll
    for (int j = 0; j < 9; j++) acc[j] = 0.f;
    for (int k = tid; k < HDIM; k += 128) {
        float xv = xr[k];
#pragma unroll
        for (int e = 0; e < NEXP; e++) acc[e] += xv * gw[k * NEXP + e];
        acc[8] += xv * sgw[k];
    }
    __shared__ float red[9][4];
#pragma unroll
    for (int j = 0; j < 9; j++) {
        float v = acc[j];
#pragma unroll
        for (int o = 16; o > 0; o >>= 1) v += __shfl_xor_sync(0xffffffffu, v, o);
        if ((tid & 31) == 0) red[j][tid >> 5] = v;
    }
    __syncthreads();
    if (tid == 0) {
        float lg[9];
#pragma unroll
        for (int j = 0; j < 9; j++) lg[j] = red[j][0] + red[j][1] + red[j][2] + red[j][3];
        float m = lg[0];
        for (int e = 1; e < NEXP; e++) m = fmaxf(m, lg[e]);
        float p[NEXP], s = 0.f;
        for (int e = 0; e < NEXP; e++) { p[e] = expf(lg[e] - m); s += p[e]; }
        for (int e = 0; e < NEXP; e++) p[e] /= s;
        int i1 = 0;
        for (int e = 1; e < NEXP; e++) if (p[e] > p[i1]) i1 = e;
        int i2 = (i1 == 0) ? 1 : 0;
        for (int e = 0; e < NEXP; e++) if (e != i1 && p[e] > p[i2]) i2 = e;
        int s1 = atomicAdd(&g_cnt[i1], 1);
        g_tok[i1 * NTOK + s1] = n;  g_wt[i1 * NTOK + s1] = p[i1];
        g_slot[n * 2] = i1 * NTOK + s1;
        int s2 = atomicAdd(&g_cnt[i2], 1);
        g_tok[i2 * NTOK + s2] = n;  g_wt[i2 * NTOK + s2] = p[i2];
        g_slot[n * 2 + 1] = i2 * NTOK + s2;
        g_sg[n] = 1.f / (1.f + expf(-lg[8]));
    }
}

// ============================================================================
// Merged gate_up GEMM + SiLU*mul  (z=0: shared, z=1..8: expert z-1)
//   A: fp16 smem (pitch 80B) + ldmatrix.  B: fp32 smem + pack_h2.
//   CTA 128m x 64f, 128 threads, 4 warps each 64m x 64n (m-half x gate/up).
//   Stage bytes: A 10240, Bg 8704, Bu 8704 = 27648. 2-stage, 3 CTAs/SM.
//   Epilogue writes fp16 activations.
// ============================================================================
#define GU_A_B  10240
#define GU_B_B  8704
#define GU_BPAD 68
#define GU_STAGE (GU_A_B + 2 * GU_B_B)          // 27648
#define GU_SMEM (2 * GU_STAGE)                  // 55296

__global__ __launch_bounds__(128, 3) void gateup_all(const float* __restrict__ Wsh,
                                                     const float* __restrict__ Wex) {
    const int z = blockIdx.z;
    const int m0 = blockIdx.y * 128;
    int F, cnt, ebase = 0;
    const float* W;
    __half* actOut;
    if (z == 0) {
        F = ISHA; cnt = NTOK; W = Wsh; actOut = g_acts_h;
    } else {
        F = IEXP;
        if (blockIdx.x >= IEXP / 64) return;
        const int e = z - 1;
        cnt = g_cnt[e];
        if (m0 >= cnt) return;
        ebase = e * NTOK;
        W = Wex + (size_t)e * HDIM * 2 * IEXP;
        actOut = g_actr_h + (size_t)e * NTOK * IEXP;
    }
    const int f0 = blockIdx.x * 64;
    const int ldw = 2 * F;
    extern __shared__ char smem[];
    const int tid = threadIdx.x;
    const int wid = tid >> 5, lane = tid & 31;
    const int gid = lane >> 2, tg = lane & 3;
    const int wm = (wid & 1) * 64;       // m-half
    const int uphalf = wid >> 1;         // 0 = gate, 1 = up
    const uint32_t sb = smem_u32(smem);
    const uint32_t laneA = (uint32_t)((lane & 15) * 80 + (lane >> 4) * 16);

    // ---- staging addressing ----
    // A (fp16): 4 chunks/thread: row = (tid>>2) + 32*i, q = tid&3 (16B chunks)
    const int aRow0 = tid >> 2, aQ = tid & 3;
    uint32_t aByte[4];
#pragma unroll
    for (int i = 0; i < 4; i++) {
        int row = aRow0 + 32 * i;
        int t;
        if (z > 0)
            t = g_tok[ebase + ((m0 + row < cnt) ? (m0 + row) : 0)];
        else
            t = m0 + row;
        aByte[i] = (uint32_t)t * (HDIM * 2);
    }
    const char* xbase = (const char*)g_xh + aQ * 16;
    const uint32_t aDst0 = sb + (uint32_t)(aRow0 * 80 + aQ * 16);
    // B (fp32): 8 chunks/thread
    const int bR0 = tid >> 4, bQ = tid & 15;
    const float* bBase = W + (size_t)bR0 * ldw + f0 + bQ * 4;
    const uint32_t bDst0 = sb + (uint32_t)(GU_A_B + bR0 * GU_BPAD * 4 + bQ * 16);

    float acc[4][8][4];
#pragma unroll
    for (int mf = 0; mf < 4; mf++)
#pragma unroll
        for (int nf = 0; nf < 8; nf++)
#pragma unroll
            for (int r = 0; r < 4; r++) acc[mf][nf][r] = 0.f;

    // ---- prologue: stage 0 ----
#pragma unroll
    for (int i = 0; i < 4; i++)
        cp16(aDst0 + (uint32_t)(i * 32 * 80), xbase + aByte[i]);
#pragma unroll
    for (int i = 0; i < 8; i++) {
        int half = i >> 2, rr = i & 3;
        cp16(bDst0 + (uint32_t)(half * GU_B_B + rr * 8 * GU_BPAD * 4),
             bBase + (size_t)(half ? F : 0) + (size_t)(rr * 8) * ldw);
    }
    CP_COMMIT();

    int buf = 0;
    const int kIters = HDIM / 32;  // 64
    for (int kt = 0; kt < kIters; kt++) {
        if (kt + 1 < kIters) {
            const uint32_t so = (uint32_t)((buf ^ 1) * GU_STAGE);
            const int k0 = (kt + 1) * 32;
#pragma unroll
            for (int i = 0; i < 4; i++)
                cp16(aDst0 + so + (uint32_t)(i * 32 * 80),
                     xbase + aByte[i] + k0 * 2);
#pragma unroll
            for (int i = 0; i < 8; i++) {
                int half = i >> 2, rr = i & 3;
                cp16(bDst0 + so + (uint32_t)(half * GU_B_B + rr * 8 * GU_BPAD * 4),
                     bBase + (size_t)(half ? F : 0) + (size_t)(k0 + rr * 8) * ldw);
            }
            CP_COMMIT();
            CP_WAIT(1);
        } else {
            CP_WAIT(0);
        }
        __syncthreads();

        const uint32_t sA = sb + (uint32_t)(buf * GU_STAGE);
        const float* Bs = reinterpret_cast<const float*>(
            smem + buf * GU_STAGE + GU_A_B + uphalf * GU_B_B);
#pragma unroll
        for (int ks = 0; ks < 2; ks++) {
            const int k0 = ks * 16;
            uint32_t a[4][4];
#pragma unroll
            for (int mf = 0; mf < 4; mf++)
                ldsm4(a[mf], sA + (uint32_t)((wm + mf * 16) * 80 + ks * 32) + laneA);
#pragma unroll
            for (int nf = 0; nf < 8; nf++) {
                int n = nf * 8 + gid;
                uint32_t b[2];
                b[0] = pack_h2(Bs[(k0 + 2 * tg) * GU_BPAD + n],
                               Bs[(k0 + 2 * tg + 1) * GU_BPAD + n]);
                b[1] = pack_h2(Bs[(k0 + 2 * tg + 8) * GU_BPAD + n],
                               Bs[(k0 + 2 * tg + 9) * GU_BPAD + n]);
#pragma unroll
                for (int mf = 0; mf < 4; mf++) mma16(acc[mf][nf], a[mf], b);
            }
        }
        __syncthreads();
        buf ^= 1;
    }

    // ---- epilogue: exchange up through smem (fp32), gate warps combine ----
    float* ex = reinterpret_cast<float*>(smem);
    if (uphalf) {
#pragma unroll
        for (int mf = 0; mf < 4; mf++)
#pragma unroll
            for (int h = 0; h < 2; h++) {
                int row = wm + mf * 16 + gid + h * 8;
#pragma unroll
                for (int nf = 0; nf < 8; nf++) {
                    int col = nf * 8 + 2 * tg;
                    ex[row * 72 + col]     = acc[mf][nf][2 * h];
                    ex[row * 72 + col + 1] = acc[mf][nf][2 * h + 1];
                }
            }
    }
    __syncthreads();
    if (!uphalf) {
#pragma unroll
        for (int mf = 0; mf < 4; mf++)
#pragma unroll
            for (int h = 0; h < 2; h++) {
                int row = wm + mf * 16 + gid + h * 8;
                __half* orow = actOut + (size_t)(m0 + row) * F + f0;
#pragma unroll
                for (int nf = 0; nf < 8; nf++) {
                    int col = nf * 8 + 2 * tg;
                    float g0 = acc[mf][nf][2 * h];
                    float g1 = acc[mf][nf][2 * h + 1];
                    float u0 = ex[row * 72 + col];
                    float u1 = ex[row * 72 + col + 1];
                    float s0 = g0 / (1.0f + __expf(-g0));
                    float s1 = g1 / (1.0f + __expf(-g1));
                    uint32_t pr = pack_h2(s0 * u0, s1 * u1);
                    *reinterpret_cast<uint32_t*>(orow + col) = pr;
                }
            }
    }
}

// ============================================================================
// Merged down GEMM, uniform split-K, fp16 A (ldmatrix) + fp32 B (pack_h2):
//   z=0..3 : shared-expert K-chunk z -> g_sp[z] (raw partials)
//   z=4..11: expert z-4 -> g_eo (weight applied)
//   CTA 128m x 128n, 128 threads, 4 warps each 64m x 64n. 44 k-iters each.
//   Stage bytes: A 10240, B 16896 = 27136. 2-stage, 3 CTAs/SM.
// ============================================================================
#define DN_A_B  10240
#define DN_BPAD 132
#define DN_B_B  (32 * DN_BPAD * 4)              // 16896
#define DN_STAGE (DN_A_B + DN_B_B)              // 27136
#define DN_SMEM (2 * DN_STAGE)                  // 54272

__global__ __launch_bounds__(128, 3) void down_all(const float* __restrict__ Wdsh,
                                                   const float* __restrict__ Wdex) {
    const int z = blockIdx.z;
    const int m0 = blockIdx.y * 128;
    int cnt, lda, ebase = 0;
    const float* Wd;
    const __half* A;
    float* dstBase;
    if (z < 4) {
        cnt = NTOK;
        lda = ISHA;
        A = g_acts_h + (size_t)z * DN_KCH;
        Wd = Wdsh + (size_t)(z * DN_KCH) * HDIM;
        dstBase = g_sp + (size_t)z * NTOK * HDIM;
    } else {
        const int e = z - 4;
        cnt = g_cnt[e];
        if (m0 >= cnt) return;
        lda = IEXP;
        ebase = e * NTOK;
        A = g_actr_h + (size_t)e * NTOK * IEXP;
        Wd = Wdex + (size_t)e * IEXP * HDIM;
        dstBase = g_eo;
    }
    const int n0 = blockIdx.x * 128;
    extern __shared__ char smem[];
    const int tid = threadIdx.x;
    const int wid = tid >> 5, lane = tid & 31;
    const int gid = lane >> 2, tg = lane & 3;
    const int wm = (wid & 1) * 64;
    const int wn = (wid >> 1) * 64;
    const int kIters = DN_KCH / 32;  // 44
    const uint32_t sb = smem_u32(smem);
    const uint32_t laneA = (uint32_t)((lane & 15) * 80 + (lane >> 4) * 16);

    // A (fp16): 4 chunks/thread
    const int aRow0 = tid >> 2, aQ = tid & 3;
    const __half* aBase = A + (size_t)(m0 + aRow0) * lda + aQ * 8;
    const size_t aStride = (size_t)32 * lda;
    const uint32_t aDst0 = sb + (uint32_t)(aRow0 * 80 + aQ * 16);
    // B (fp32): 8 chunks/thread
    const int bR0 = tid >> 5, bQ = tid & 31;
    const float* bBase = Wd + (size_t)bR0 * HDIM + n0 + bQ * 4;
    const uint32_t bDst0 = sb + (uint32_t)(DN_A_B + bR0 * DN_BPAD * 4 + bQ * 16);

    float acc[4][8][4];
#pragma unroll
    for (int mf = 0; mf < 4; mf++)
#pragma unroll
        for (int nf = 0; nf < 8; nf++)
#pragma unroll
            for (int r = 0; r < 4; r++) acc[mf][nf][r] = 0.f;

#pragma unroll
    for (int i = 0; i < 4; i++)
        cp16(aDst0 + (uint32_t)(i * 32 * 80), aBase + (size_t)i * aStride);
#pragma unroll
    for (int i = 0; i < 8; i++)
        cp16(bDst0 + (uint32_t)(i * 4 * DN_BPAD * 4), bBase + (size_t)(i * 4) * HDIM);
    CP_COMMIT();

    int buf = 0;
    for (int kt = 0; kt < kIters; kt++) {
        if (kt + 1 < kIters) {
            const uint32_t so = (uint32_t)((buf ^ 1) * DN_STAGE);
            const int k0 = (kt + 1) * 32;
#pragma unroll
            for (int i = 0; i < 4; i++)
                cp16(aDst0 + so + (uint32_t)(i * 32 * 80),
                     aBase + (size_t)i * aStride + k0);
#pragma unroll
            for (int i = 0; i < 8; i++)
                cp16(bDst0 + so + (uint32_t)(i * 4 * DN_BPAD * 4),
                     bBase + (size_t)(k0 + i * 4) * HDIM);
            CP_COMMIT();
            CP_WAIT(1);
        } else {
            CP_WAIT(0);
        }
        __syncthreads();

        const uint32_t sA = sb + (uint32_t)(buf * DN_STAGE);
        const float* Bs = reinterpret_cast<const float*>(smem + buf * DN_STAGE + DN_A_B);
#pragma unroll
        for (int ks = 0; ks < 2; ks++) {
            const int k0 = ks * 16;
            uint32_t a[4][4];
#pragma unroll
            for (int mf = 0; mf < 4; mf++)
                ldsm4(a[mf], sA + (uint32_t)((wm + mf * 16) * 80 + ks * 32) + laneA);
#pragma unroll
            for (int nf = 0; nf < 8; nf++) {
                int n = wn + nf * 8 + gid;
                uint32_t b[2];
                b[0] = pack_h2(Bs[(k0 + 2 * tg) * DN_BPAD + n],
                               Bs[(k0 + 2 * tg + 1) * DN_BPAD + n]);
                b[1] = pack_h2(Bs[(k0 + 2 * tg + 8) * DN_BPAD + n],
                               Bs[(k0 + 2 * tg + 9) * DN_BPAD + n]);
#pragma unroll
                for (int mf = 0; mf < 4; mf++) mma16(acc[mf][nf], a[mf], b);
            }
        }
        __syncthreads();
        buf ^= 1;
    }

    // Epilogue
#pragma unroll
    for (int mf = 0; mf < 4; mf++) {
#pragma unroll
        for (int h = 0; h < 2; h++) {
            int slot = m0 + wm + mf * 16 + gid + h * 8;
            if (z < 4) {
                float* orow = dstBase + (size_t)slot * HDIM;
#pragma unroll
                for (int nf = 0; nf < 8; nf++) {
                    int col = n0 + wn + nf * 8 + 2 * tg;
                    orow[col]     = acc[mf][nf][2 * h];
                    orow[col + 1] = acc[mf][nf][2 * h + 1];
                }
            } else {
                if (slot >= cnt) continue;
                float wv = g_wt[ebase + slot];
                float* orow = dstBase + (size_t)(ebase + slot) * HDIM;
#pragma unroll
                for (int nf = 0; nf < 8; nf++) {
                    int col = n0 + wn + nf * 8 + 2 * tg;
                    orow[col]     = wv * acc[mf][nf][2 * h];
                    orow[col + 1] = wv * acc[mf][nf][2 * h + 1];
                }
            }
        }
    }
}

// ============================================================================
// Combine: out[token] = sg * (sp0+sp1+sp2+sp3) + eo[slotA] + eo[slotB]
// ============================================================================
__global__ void combine_kernel(float* __restrict__ out) {
    const int n = blockIdx.x;
    const int tid = threadIdx.x;  // 256
    const float sg = g_sg[n];
    const size_t rowOff = (size_t)n * (HDIM / 4);
    const size_t r0 = (size_t)g_slot[n * 2] * (HDIM / 4);
    const size_t r1 = (size_t)g_slot[n * 2 + 1] * (HDIM / 4);
    const float4* sp = reinterpret_cast<const float4*>(g_sp);
    const float4* eo = reinterpret_cast<const float4*>(g_eo);
    float4* o = reinterpret_cast<float4*>(out) + rowOff;
    const size_t spStride = (size_t)NTOK * (HDIM / 4);
#pragma unroll
    for (int i = 0; i < 2; i++) {
        int idx = tid + i * 256;
        float4 p0 = sp[rowOff + idx];
        float4 p1 = sp[spStride + rowOff + idx];
        float4 p2 = sp[2 * spStride + rowOff + idx];
        float4 p3 = sp[3 * spStride + rowOff + idx];
        float4 a = eo[r0 + idx], b = eo[r1 + idx];
        float4 v;
        v.x = sg * (p0.x + p1.x + p2.x + p3.x) + a.x + b.x;
        v.y = sg * (p0.y + p1.y + p2.y + p3.y) + a.y + b.y;
        v.z = sg * (p0.z + p1.z + p2.z + p3.z) + a.z + b.z;
        v.w = sg * (p0.w + p1.w + p2.w + p3.w) + a.w + b.w;
        o[idx] = v;
    }
}

// ============================================================================
// Launch
// ============================================================================
extern "C" void kernel_launch(void* const* d_in, const int* in_sizes, int n_in,
                              void* d_out, int out_size) {
    const float* x = (const float*)d_in[0];       // [1024, 2048]
    const float* gw = (const float*)d_in[1];      // [2048, 8]
    const float* wgu = (const float*)d_in[2];     // [8, 2048, 2816]
    const float* wdn = (const float*)d_in[3];     // [8, 1408, 2048]
    const float* swgu = (const float*)d_in[4];    // [2048, 11264]
    const float* swdn = (const float*)d_in[5];    // [5632, 2048]
    const float* sgw = (const float*)d_in[6];     // [2048, 1]
    float* out = (float*)d_out;                   // [1024, 2048]

    cudaFuncSetAttribute(gateup_all, cudaFuncAttributeMaxDynamicSharedMemorySize, GU_SMEM);
    cudaFuncSetAttribute(down_all, cudaFuncAttributeMaxDynamicSharedMemorySize, DN_SMEM);

    zero_kernel<<<1, 32>>>();
    cvtx_kernel<<<NTOK * HDIM / 8 / 256, 256>>>(x);
    router_kernel<<<NTOK, 128>>>(x, gw, sgw);

    // All gate_up GEMMs (shared z=0 + experts z=1..8) in one launch.
    gateup_all<<<dim3(ISHA / 64, NTOK / 128, 1 + NEXP), 128, GU_SMEM>>>(swgu, wgu);

    // All down GEMMs, uniform K=1408 chunks:
    //   z=0..3 shared partials -> g_sp, z=4..11 experts -> g_eo.
    down_all<<<dim3(HDIM / 128, NTOK / 128, 4 + NEXP), 128, DN_SMEM>>>(swdn, wdn);

    // Final combine: shared partial sum * sigmoid gate + two expert rows.
    combine_kernel<<<NTOK, 256>>>(out);
}

// round 16
// speedup vs baseline: 1.6035x; 1.0243x over previous
#include <cuda_runtime.h>
#include <cuda_fp16.h>
#include <cstdint>

// ============================================================================
// Problem constants
// ============================================================================
#define NTOK 1024
#define HDIM 2048
#define NEXP 8
#define IEXP 1408
#define ISHA 5632
#define DN_KCH 1408          // uniform down-GEMM K chunk (= IEXP, = ISHA/4)

// ============================================================================
// Scratch (allocation-free rule: __device__ globals)
// ============================================================================
__device__ __half g_xh[(size_t)NTOK * HDIM];             // x in fp16 (4MB)
__device__ __half g_acts_h[(size_t)NTOK * ISHA];         // shared act fp16 (11.5MB)
__device__ __half g_actr_h[(size_t)NEXP * NTOK * IEXP];  // routed act fp16 (23MB)
__device__ float  g_eo[(size_t)NEXP * NTOK * HDIM];      // routed expert out (67MB)
__device__ float  g_sp[(size_t)4 * NTOK * HDIM];         // shared down partials (32MB)
__device__ float  g_sg[NTOK];
__device__ int    g_cnt[NEXP];
__device__ int    g_tok[NEXP * NTOK];
__device__ float  g_wt[NEXP * NTOK];
__device__ int    g_slot[NTOK * 2];

// ============================================================================
// Helpers
// ============================================================================
__device__ __forceinline__ uint32_t smem_u32(const void* p) {
    uint32_t a;
    asm("{ .reg .u64 t; cvta.to.shared.u64 t, %1; cvt.u32.u64 %0, t; }" : "=r"(a) : "l"(p));
    return a;
}

__device__ __forceinline__ uint32_t pack_h2(float a, float b) {
    uint32_t r;
    asm("cvt.rn.f16x2.f32 %0, %1, %2;" : "=r"(r) : "f"(b), "f"(a));
    return r;
}

__device__ __forceinline__ void cp16(uint32_t dst, const void* src) {
    asm volatile("cp.async.cg.shared.global [%0], [%1], 16;" :: "r"(dst), "l"(src));
}
#define CP_COMMIT() asm volatile("cp.async.commit_group;" ::: "memory")
#define CP_WAIT(n)  asm volatile("cp.async.wait_group %0;" :: "n"(n) : "memory")

// m16n8k16 fp16 mma, fp32 accumulate
__device__ __forceinline__ void mma16(float* d, const uint32_t* a, const uint32_t* b) {
    asm volatile(
        "mma.sync.aligned.m16n8k16.row.col.f32.f16.f16.f32 "
        "{%0,%1,%2,%3}, {%4,%5,%6,%7}, {%8,%9}, {%0,%1,%2,%3};"
        : "+f"(d[0]), "+f"(d[1]), "+f"(d[2]), "+f"(d[3])
        : "r"(a[0]), "r"(a[1]), "r"(a[2]), "r"(a[3]), "r"(b[0]), "r"(b[1]));
}

__device__ __forceinline__ void ldsm4(uint32_t* r, uint32_t addr) {
    asm volatile("ldmatrix.sync.aligned.m8n8.x4.shared.b16 {%0,%1,%2,%3}, [%4];"
        : "=r"(r[0]), "=r"(r[1]), "=r"(r[2]), "=r"(r[3]) : "r"(addr));
}
__device__ __forceinline__ void ldsm4t(uint32_t* r, uint32_t addr) {
    asm volatile("ldmatrix.sync.aligned.m8n8.x4.trans.shared.b16 {%0,%1,%2,%3}, [%4];"
        : "=r"(r[0]), "=r"(r[1]), "=r"(r[2]), "=r"(r[3]) : "r"(addr));
}

// ============================================================================
// Small kernels
// ============================================================================
__global__ void zero_kernel() {
    if (threadIdx.x < NEXP) g_cnt[threadIdx.x] = 0;
}

// x fp32 -> fp16 (rne), 8 elems per thread
__global__ void cvtx_kernel(const float* __restrict__ x) {
    int idx = blockIdx.x * 256 + threadIdx.x;
    const float4* s = reinterpret_cast<const float4*>(x) + (size_t)idx * 2;
    float4 v0 = s[0], v1 = s[1];
    uint4 o;
    o.x = pack_h2(v0.x, v0.y);
    o.y = pack_h2(v0.z, v0.w);
    o.z = pack_h2(v1.x, v1.y);
    o.w = pack_h2(v1.z, v1.w);
    reinterpret_cast<uint4*>(g_xh)[idx] = o;
}

// ============================================================================
// Router
// ============================================================================
__global__ void router_kernel(const float* __restrict__ x,
                              const float* __restrict__ gw,
                              const float* __restrict__ sgw) {
    const int n = blockIdx.x;
    const int tid = threadIdx.x;  // 128
    const float* xr = x + (size_t)n * HDIM;
    float acc[9];
#pragma unroll
    for (int j = 0; j < 9; j++) acc[j] = 0.f;
    for (int k = tid; k < HDIM; k += 128) {
        float xv = xr[k];
#pragma unroll
        for (int e = 0; e < NEXP; e++) acc[e] += xv * gw[k * NEXP + e];
        acc[8] += xv * sgw[k];
    }
    __shared__ float red[9][4];
#pragma unroll
    for (int j = 0; j < 9; j++) {
        float v = acc[j];
#pragma unroll
        for (int o = 16; o > 0; o >>= 1) v += __shfl_xor_sync(0xffffffffu, v, o);
        if ((tid & 31) == 0) red[j][tid >> 5] = v;
    }
    __syncthreads();
    if (tid == 0) {
        float lg[9];
#pragma unroll
        for (int j = 0; j < 9; j++) lg[j] = red[j][0] + red[j][1] + red[j][2] + red[j][3];
        float m = lg[0];
        for (int e = 1; e < NEXP; e++) m = fmaxf(m, lg[e]);
        float p[NEXP], s = 0.f;
        for (int e = 0; e < NEXP; e++) { p[e] = expf(lg[e] - m); s += p[e]; }
        for (int e = 0; e < NEXP; e++) p[e] /= s;
        int i1 = 0;
        for (int e = 1; e < NEXP; e++) if (p[e] > p[i1]) i1 = e;
        int i2 = (i1 == 0) ? 1 : 0;
        for (int e = 0; e < NEXP; e++) if (e != i1 && p[e] > p[i2]) i2 = e;
        int s1 = atomicAdd(&g_cnt[i1], 1);
        g_tok[i1 * NTOK + s1] = n;  g_wt[i1 * NTOK + s1] = p[i1];
        g_slot[n * 2] = i1 * NTOK + s1;
        int s2 = atomicAdd(&g_cnt[i2], 1);
        g_tok[i2 * NTOK + s2] = n;  g_wt[i2 * NTOK + s2] = p[i2];
        g_slot[n * 2 + 1] = i2 * NTOK + s2;
        g_sg[n] = 1.f / (1.f + expf(-lg[8]));
    }
}

// ============================================================================
// Merged gate_up GEMM + SiLU*mul  (z=0: shared, z=1..8: expert z-1)
//   A: fp16 smem (pitch 80B) + ldmatrix.
//   B: fp32 cp.async staged, cooperative smem convert -> fp16 (pitch 144B),
//      fragments via ldmatrix.x4.trans.
//   CTA 128m x 64f, 128 threads, 4 warps each 64m x 64n (m-half x gate/up).
//   smem: 2 x (A 10240 + rawB 2x8704) + h16B 2x4608 = 64512 B. 3 CTAs/SM.
// ============================================================================
#define GU_A_B   10240
#define GU_RAWB  8704                            // 32 x 68 fp32, per half
#define GU_STAGE (GU_A_B + 2 * GU_RAWB)          // 27648
#define GU_H16   4608                            // 32 x 144B, per half
#define GU_SMEM  (2 * GU_STAGE + 2 * GU_H16)     // 64512

__global__ __launch_bounds__(128, 3) void gateup_all(const float* __restrict__ Wsh,
                                                     const float* __restrict__ Wex) {
    const int z = blockIdx.z;
    const int m0 = blockIdx.y * 128;
    int F, cnt, ebase = 0;
    const float* W;
    __half* actOut;
    if (z == 0) {
        F = ISHA; cnt = NTOK; W = Wsh; actOut = g_acts_h;
    } else {
        F = IEXP;
        if (blockIdx.x >= IEXP / 64) return;
        const int e = z - 1;
        cnt = g_cnt[e];
        if (m0 >= cnt) return;
        ebase = e * NTOK;
        W = Wex + (size_t)e * HDIM * 2 * IEXP;
        actOut = g_actr_h + (size_t)e * NTOK * IEXP;
    }
    const int f0 = blockIdx.x * 64;
    const int ldw = 2 * F;
    extern __shared__ char smem[];
    const int tid = threadIdx.x;
    const int wid = tid >> 5, lane = tid & 31;
    const int gid = lane >> 2, tg = lane & 3;
    const int wm = (wid & 1) * 64;       // m-half
    const int uphalf = wid >> 1;         // 0 = gate, 1 = up
    const int grp = lane >> 3, li = lane & 7;
    const uint32_t sb = smem_u32(smem);
    const uint32_t laneA = (uint32_t)((lane & 15) * 80 + (lane >> 4) * 16);
    const uint32_t laneB = (uint32_t)(((grp & 1) * 8 + li) * 144 + (grp >> 1) * 16);

    // ---- staging addressing ----
    const int aRow0 = tid >> 2, aQ = tid & 3;
    uint32_t aByte[4];
#pragma unroll
    for (int i = 0; i < 4; i++) {
        int row = aRow0 + 32 * i;
        int t;
        if (z > 0)
            t = g_tok[ebase + ((m0 + row < cnt) ? (m0 + row) : 0)];
        else
            t = m0 + row;
        aByte[i] = (uint32_t)t * (HDIM * 2);
    }
    const char* xbase = (const char*)g_xh + aQ * 16;
    const uint32_t aDst0 = sb + (uint32_t)(aRow0 * 80 + aQ * 16);
    const int bR0 = tid >> 4, bQ = tid & 15;
    const float* bBase = W + (size_t)bR0 * ldw + f0 + bQ * 4;
    const uint32_t bDst0 = sb + (uint32_t)(GU_A_B + bR0 * 272 + bQ * 16);

    float acc[4][8][4];
#pragma unroll
    for (int mf = 0; mf < 4; mf++)
#pragma unroll
        for (int nf = 0; nf < 8; nf++)
#pragma unroll
            for (int r = 0; r < 4; r++) acc[mf][nf][r] = 0.f;

    // ---- prologue: stage 0 into buf 0 ----
#pragma unroll
    for (int i = 0; i < 4; i++)
        cp16(aDst0 + (uint32_t)(i * 32 * 80), xbase + aByte[i]);
#pragma unroll
    for (int i = 0; i < 8; i++) {
        int half = i >> 2, rr = i & 3;
        cp16(bDst0 + (uint32_t)(half * GU_RAWB + rr * 8 * 272),
             bBase + (size_t)(half ? F : 0) + (size_t)(rr * 8) * ldw);
    }
    CP_COMMIT();

    int buf = 0;
    const int kIters = HDIM / 32;  // 64
    for (int kt = 0; kt < kIters; kt++) {
        CP_WAIT(0);
        __syncthreads();                 // stage(buf) visible; prev compute done
        if (kt + 1 < kIters) {
            const uint32_t so = (uint32_t)((buf ^ 1) * GU_STAGE);
            const int k0 = (kt + 1) * 32;
#pragma unroll
            for (int i = 0; i < 4; i++)
                cp16(aDst0 + so + (uint32_t)(i * 32 * 80),
                     xbase + aByte[i] + k0 * 2);
#pragma unroll
            for (int i = 0; i < 8; i++) {
                int half = i >> 2, rr = i & 3;
                cp16(bDst0 + so + (uint32_t)(half * GU_RAWB + rr * 8 * 272),
                     bBase + (size_t)(half ? F : 0) + (size_t)(k0 + rr * 8) * ldw);
            }
            CP_COMMIT();
        }

        // ---- cooperative convert rawB(buf) fp32 -> h16 (once per CTA) ----
        {
            const char* rawB = smem + buf * GU_STAGE + GU_A_B;
            char* h16B = smem + 2 * GU_STAGE;
#pragma unroll
            for (int j = 0; j < 8; j++) {
                int c = tid + j * 128;           // 0..1023
                int half = c >> 9, rem = c & 511;
                int k = rem >> 4, q = rem & 15;
                float4 v = *reinterpret_cast<const float4*>(
                    rawB + half * GU_RAWB + k * 272 + q * 16);
                uint2 o;
                o.x = pack_h2(v.x, v.y);
                o.y = pack_h2(v.z, v.w);
                *reinterpret_cast<uint2*>(h16B + half * GU_H16 + k * 144 + q * 8) = o;
            }
        }
        __syncthreads();                 // h16 ready

        const uint32_t sA = sb + (uint32_t)(buf * GU_STAGE);
        const uint32_t sB = sb + (uint32_t)(2 * GU_STAGE + uphalf * GU_H16);
#pragma unroll
        for (int ks = 0; ks < 2; ks++) {
            uint32_t a[4][4];
#pragma unroll
            for (int mf = 0; mf < 4; mf++)
                ldsm4(a[mf], sA + (uint32_t)((wm + mf * 16) * 80 + ks * 32) + laneA);
#pragma unroll
            for (int p = 0; p < 4; p++) {
                uint32_t b[4];
                ldsm4t(b, sB + (uint32_t)(ks * 16 * 144 + p * 32) + laneB);
#pragma unroll
                for (int mf = 0; mf < 4; mf++) {
                    mma16(acc[mf][2 * p], a[mf], b);
                    mma16(acc[mf][2 * p + 1], a[mf], b + 2);
                }
            }
        }
        buf ^= 1;
    }
    __syncthreads();                     // drain before smem reuse in epilogue

    // ---- epilogue: up warps stash via smem (fp32), gate warps combine ----
    float* ex = reinterpret_cast<float*>(smem);
    if (uphalf) {
#pragma unroll
        for (int mf = 0; mf < 4; mf++)
#pragma unroll
            for (int h = 0; h < 2; h++) {
                int row = wm + mf * 16 + gid + h * 8;
#pragma unroll
                for (int nf = 0; nf < 8; nf++) {
                    int col = nf * 8 + 2 * tg;
                    ex[row * 72 + col]     = acc[mf][nf][2 * h];
                    ex[row * 72 + col + 1] = acc[mf][nf][2 * h + 1];
                }
            }
    }
    __syncthreads();
    if (!uphalf) {
#pragma unroll
        for (int mf = 0; mf < 4; mf++)
#pragma unroll
            for (int h = 0; h < 2; h++) {
                int row = wm + mf * 16 + gid + h * 8;
                __half* orow = actOut + (size_t)(m0 + row) * F + f0;
#pragma unroll
                for (int nf = 0; nf < 8; nf++) {
                    int col = nf * 8 + 2 * tg;
                    float g0 = acc[mf][nf][2 * h];
                    float g1 = acc[mf][nf][2 * h + 1];
                    float u0 = ex[row * 72 + col];
                    float u1 = ex[row * 72 + col + 1];
                    float s0 = g0 / (1.0f + __expf(-g0));
                    float s1 = g1 / (1.0f + __expf(-g1));
                    uint32_t pr = pack_h2(s0 * u0, s1 * u1);
                    *reinterpret_cast<uint32_t*>(orow + col) = pr;
                }
            }
    }
}

// ============================================================================
// Merged down GEMM, uniform split-K:
//   z=0..3 : shared-expert K-chunk z -> g_sp[z] (raw partials)
//   z=4..11: expert z-4 -> g_eo (weight applied)
//   A fp16 (ldmatrix), B fp32 staged -> smem convert -> fp16 (ldsm4t).
//   CTA 128m x 128n, 128 threads, 4 warps each 64m x 64n. 44 k-iters.
//   smem: 2 x (A 10240 + rawB 16896) + h16B 8704 = 62976 B. 3 CTAs/SM.
// ============================================================================
#define DN_A_B   10240
#define DN_RAWB  16896                           // 32 x 132 fp32
#define DN_STAGE (DN_A_B + DN_RAWB)              // 27136
#define DN_H16   8704                            // 32 x 272B
#define DN_SMEM  (2 * DN_STAGE + DN_H16)         // 62976

__global__ __launch_bounds__(128, 3) void down_all(const float* __restrict__ Wdsh,
                                                   const float* __restrict__ Wdex) {
    const int z = blockIdx.z;
    const int m0 = blockIdx.y * 128;
    int cnt, lda, ebase = 0;
    const float* Wd;
    const __half* A;
    float* dstBase;
    if (z < 4) {
        cnt = NTOK;
        lda = ISHA;
        A = g_acts_h + (size_t)z * DN_KCH;
        Wd = Wdsh + (size_t)(z * DN_KCH) * HDIM;
        dstBase = g_sp + (size_t)z * NTOK * HDIM;
    } else {
        const int e = z - 4;
        cnt = g_cnt[e];
        if (m0 >= cnt) return;
        lda = IEXP;
        ebase = e * NTOK;
        A = g_actr_h + (size_t)e * NTOK * IEXP;
        Wd = Wdex + (size_t)e * IEXP * HDIM;
        dstBase = g_eo;
    }
    const int n0 = blockIdx.x * 128;
    extern __shared__ char smem[];
    const int tid = threadIdx.x;
    const int wid = tid >> 5, lane = tid & 31;
    const int gid = lane >> 2, tg = lane & 3;
    const int wm = (wid & 1) * 64;
    const int wn = (wid >> 1) * 64;
    const int grp = lane >> 3, li = lane & 7;
    const int kIters = DN_KCH / 32;  // 44
    const uint32_t sb = smem_u32(smem);
    const uint32_t laneA = (uint32_t)((lane & 15) * 80 + (lane >> 4) * 16);
    const uint32_t laneB = (uint32_t)(((grp & 1) * 8 + li) * 272 + (grp >> 1) * 16);

    // A: 4 chunks/thread (slot rows clamped to stay in this expert's region)
    const int aRow0 = tid >> 2, aQ = tid & 3;
    const __half* aSrc[4];
#pragma unroll
    for (int i = 0; i < 4; i++) {
        int row = m0 + aRow0 + 32 * i;
        if (row >= NTOK) row = NTOK - 1;
        aSrc[i] = A + (size_t)row * lda + aQ * 8;
    }
    const uint32_t aDst0 = sb + (uint32_t)(aRow0 * 80 + aQ * 16);
    // B: 8 chunks/thread (fp32 raw)
    const int bR0 = tid >> 5, bQ = tid & 31;
    const float* bBase = Wd + (size_t)bR0 * HDIM + n0 + bQ * 4;
    const uint32_t bDst0 = sb + (uint32_t)(DN_A_B + bR0 * 528 + bQ * 16);

    float acc[4][8][4];
#pragma unroll
    for (int mf = 0; mf < 4; mf++)
#pragma unroll
        for (int nf = 0; nf < 8; nf++)
#pragma unroll
            for (int r = 0; r < 4; r++) acc[mf][nf][r] = 0.f;

    // ---- prologue ----
#pragma unroll
    for (int i = 0; i < 4; i++)
        cp16(aDst0 + (uint32_t)(i * 32 * 80), aSrc[i]);
#pragma unroll
    for (int i = 0; i < 8; i++)
        cp16(bDst0 + (uint32_t)(i * 4 * 528), bBase + (size_t)(i * 4) * HDIM);
    CP_COMMIT();

    int buf = 0;
    for (int kt = 0; kt < kIters; kt++) {
        CP_WAIT(0);
        __syncthreads();
        if (kt + 1 < kIters) {
            const uint32_t so = (uint32_t)((buf ^ 1) * DN_STAGE);
            const int k0 = (kt + 1) * 32;
#pragma unroll
            for (int i = 0; i < 4; i++)
                cp16(aDst0 + so + (uint32_t)(i * 32 * 80), aSrc[i] + k0);
#pragma unroll
            for (int i = 0; i < 8; i++)
                cp16(bDst0 + so + (uint32_t)(i * 4 * 528),
                     bBase + (size_t)(k0 + i * 4) * HDIM);
            CP_COMMIT();
        }

        // ---- cooperative convert rawB(buf) -> h16 ----
        {
            const char* rawB = smem + buf * DN_STAGE + DN_A_B;
            char* h16B = smem + 2 * DN_STAGE;
#pragma unroll
            for (int j = 0; j < 8; j++) {
                int c = tid + j * 128;           // 0..1023
                int k = c >> 5, q = c & 31;
                float4 v = *reinterpret_cast<const float4*>(rawB + k * 528 + q * 16);
                uint2 o;
                o.x = pack_h2(v.x, v.y);
                o.y = pack_h2(v.z, v.w);
                *reinterpret_cast<uint2*>(h16B + k * 272 + q * 8) = o;
            }
        }
        __syncthreads();

        const uint32_t sA = sb + (uint32_t)(buf * DN_STAGE);
        const uint32_t sB = sb + (uint32_t)(2 * DN_STAGE);
#pragma unroll
        for (int ks = 0; ks < 2; ks++) {
            uint32_t a[4][4];
#pragma unroll
            for (int mf = 0; mf < 4; mf++)
                ldsm4(a[mf], sA + (uint32_t)((wm + mf * 16) * 80 + ks * 32) + laneA);
#pragma unroll
            for (int p = 0; p < 4; p++) {
                uint32_t b[4];
                ldsm4t(b, sB + (uint32_t)(ks * 16 * 272 + (wn + p * 16) * 2) + laneB);
#pragma unroll
                for (int mf = 0; mf < 4; mf++) {
                    mma16(acc[mf][2 * p], a[mf], b);
                    mma16(acc[mf][2 * p + 1], a[mf], b + 2);
                }
            }
        }
        buf ^= 1;
    }

    // Epilogue
#pragma unroll
    for (int mf = 0; mf < 4; mf++) {
#pragma unroll
        for (int h = 0; h < 2; h++) {
            int slot = m0 + wm + mf * 16 + gid + h * 8;
            if (z < 4) {
                float* orow = dstBase + (size_t)slot * HDIM;
#pragma unroll
                for (int nf = 0; nf < 8; nf++) {
                    int col = n0 + wn + nf * 8 + 2 * tg;
                    orow[col]     = acc[mf][nf][2 * h];
                    orow[col + 1] = acc[mf][nf][2 * h + 1];
                }
            } else {
                if (slot >= cnt) continue;
                float wv = g_wt[ebase + slot];
                float* orow = dstBase + (size_t)(ebase + slot) * HDIM;
#pragma unroll
                for (int nf = 0; nf < 8; nf++) {
                    int col = n0 + wn + nf * 8 + 2 * tg;
                    orow[col]     = wv * acc[mf][nf][2 * h];
                    orow[col + 1] = wv * acc[mf][nf][2 * h + 1];
                }
            }
        }
    }
}

// ============================================================================
// Combine: out[token] = sg * (sp0+sp1+sp2+sp3) + eo[slotA] + eo[slotB]
// ============================================================================
__global__ void combine_kernel(float* __restrict__ out) {
    const int n = blockIdx.x;
    const int tid = threadIdx.x;  // 256
    const float sg = g_sg[n];
    const size_t rowOff = (size_t)n * (HDIM / 4);
    const size_t r0 = (size_t)g_slot[n * 2] * (HDIM / 4);
    const size_t r1 = (size_t)g_slot[n * 2 + 1] * (HDIM / 4);
    const float4* sp = reinterpret_cast<const float4*>(g_sp);
    const float4* eo = reinterpret_cast<const float4*>(g_eo);
    float4* o = reinterpret_cast<float4*>(out) + rowOff;
    const size_t spStride = (size_t)NTOK * (HDIM / 4);
#pragma unroll
    for (int i = 0; i < 2; i++) {
        int idx = tid + i * 256;
        float4 p0 = sp[rowOff + idx];
        float4 p1 = sp[spStride + rowOff + idx];
        float4 p2 = sp[2 * spStride + rowOff + idx];
        float4 p3 = sp[3 * spStride + rowOff + idx];
        float4 a = eo[r0 + idx], b = eo[r1 + idx];
        float4 v;
        v.x = sg * (p0.x + p1.x + p2.x + p3.x) + a.x + b.x;
        v.y = sg * (p0.y + p1.y + p2.y + p3.y) + a.y + b.y;
        v.z = sg * (p0.z + p1.z + p2.z + p3.z) + a.z + b.z;
        v.w = sg * (p0.w + p1.w + p2.w + p3.w) + a.w + b.w;
        o[idx] = v;
    }
}

// ============================================================================
// Launch
// ============================================================================
extern "C" void kernel_launch(void* const* d_in, const int* in_sizes, int n_in,
                              void* d_out, int out_size) {
    const float* x = (const float*)d_in[0];       // [1024, 2048]
    const float* gw = (const float*)d_in[1];      // [2048, 8]
    const float* wgu = (const float*)d_in[2];     // [8, 2048, 2816]
    const float* wdn = (const float*)d_in[3];     // [8, 1408, 2048]
    const float* swgu = (const float*)d_in[4];    // [2048, 11264]
    const float* swdn = (const float*)d_in[5];    // [5632, 2048]
    const float* sgw = (const float*)d_in[6];     // [2048, 1]
    float* out = (float*)d_out;                   // [1024, 2048]

    cudaFuncSetAttribute(gateup_all, cudaFuncAttributeMaxDynamicSharedMemorySize, GU_SMEM);
    cudaFuncSetAttribute(down_all, cudaFuncAttributeMaxDynamicSharedMemorySize, DN_SMEM);

    zero_kernel<<<1, 32>>>();
    cvtx_kernel<<<NTOK * HDIM / 8 / 256, 256>>>(x);
    router_kernel<<<NTOK, 128>>>(x, gw, sgw);

    // All gate_up GEMMs (shared z=0 + experts z=1..8) in one launch.
    gateup_all<<<dim3(ISHA / 64, NTOK / 128, 1 + NEXP), 128, GU_SMEM>>>(swgu, wgu);

    // All down GEMMs, uniform K=1408 chunks:
    //   z=0..3 shared partials -> g_sp, z=4..11 experts -> g_eo.
    down_all<<<dim3(HDIM / 128, NTOK / 128, 4 + NEXP), 128, DN_SMEM>>>(swdn, wdn);

    // Final combine: shared partial sum * sigmoid gate + two expert rows.
    combine_kernel<<<NTOK, 256>>>(out);
}